// round 3
// baseline (speedup 1.0000x reference)
#include <cuda_runtime.h>
#include <math.h>
#include <stdint.h>

// ---------------- problem constants ----------------
static const int BB    = 8;
static const int NR    = 1024;
static const int NSEQ  = 2048;     // N = NR + NC
static const int FEAT  = 768;
static const int HIDD  = 256;
static const int GATD  = 128;
static const int GRUD  = 64;
static const int MTOT  = BB * NSEQ;   // 16384

// ---------------- scratch (static device memory; no allocs) ----------------
__device__ float g_x   [BB * NSEQ * FEAT];   // concat input
__device__ float g_proj[BB * NSEQ * HIDD];
__device__ float g_h1  [BB * NSEQ * HIDD];   // GAT1 h
__device__ float g_g1  [BB * NSEQ * HIDD];   // GAT1 out (relu+mask)
__device__ float g_h2  [BB * NSEQ * GATD];   // GAT2 h
__device__ float g_gat [BB * NSEQ * GATD];   // GAT2 out (mask)
__device__ float g_s1s [BB * NSEQ];
__device__ float g_s1d [BB * NSEQ];
__device__ float g_s2s [BB * NSEQ];
__device__ float g_s2d [BB * NSEQ];
__device__ float g_xf  [BB * NSEQ * 3 * GRUD];
__device__ float g_xb  [BB * NSEQ * 3 * GRUD];
__device__ float g_gf  [BB * NSEQ * GRUD];
__device__ float g_gb  [BB * NSEQ * GRUD];
__device__ float g_pool[BB * 2 * GRUD];

// ---------------- f32x2 packed math helpers (Blackwell) ----------------
__device__ __forceinline__ unsigned long long pk2(float lo, float hi) {
    unsigned long long r;
    asm("mov.b64 %0, {%1, %2};" : "=l"(r) : "f"(lo), "f"(hi));
    return r;
}
__device__ __forceinline__ void upk2(unsigned long long v, float& lo, float& hi) {
    asm("mov.b64 {%0, %1}, %2;" : "=f"(lo), "=f"(hi) : "l"(v));
}
__device__ __forceinline__ unsigned long long ffma2(unsigned long long a,
                                                    unsigned long long b,
                                                    unsigned long long c) {
    unsigned long long d;
    asm("fma.rn.f32x2 %0, %1, %2, %3;" : "=l"(d) : "l"(a), "l"(b), "l"(c));
    return d;
}
__device__ __forceinline__ unsigned long long fadd2(unsigned long long a,
                                                    unsigned long long b) {
    unsigned long long d;
    asm("add.rn.f32x2 %0, %1, %2;" : "=l"(d) : "l"(a), "l"(b));
    return d;
}

// ---------------- concat req||code -> g_x ----------------
__global__ void concat_kernel(const float4* __restrict__ req,
                              const float4* __restrict__ code,
                              float4* __restrict__ x) {
    size_t idx = (size_t)blockIdx.x * blockDim.x + threadIdx.x;
    const size_t TOT = (size_t)BB * NSEQ * (FEAT / 4);
    if (idx >= TOT) return;
    const int ROW4 = FEAT / 4;  // 192
    int b   = (int)(idx / ((size_t)NSEQ * ROW4));
    int rem = (int)(idx % ((size_t)NSEQ * ROW4));
    int i   = rem / ROW4;
    int c   = rem % ROW4;
    float4 v;
    if (i < NR) v = req [((size_t)b * NR + i) * ROW4 + c];
    else        v = code[((size_t)b * NR + (i - NR)) * ROW4 + c];
    x[idx] = v;
}

// ---------------- tiled SGEMM: C[M,Dout] = act(A[M,K] @ W[Dout,K]^T + bias) ----------------
// BM=128 BN=64 BK=16, 256 threads, 8x4 per thread.
template <int ACT>
__global__ __launch_bounds__(256)
void gemm_kernel(const float* __restrict__ A, const float* __restrict__ W,
                 const float* __restrict__ bias, float* __restrict__ C,
                 int M, int K, int Dout) {
    const int BM = 128, BN = 64, BK = 16;
    __shared__ float Ast[BK][BM];
    __shared__ float Wt [BK][BN];
    int tid = threadIdx.x;
    int tx = tid & 15;   // n group (4 cols)
    int ty = tid >> 4;   // m group (8 rows)
    int m0 = blockIdx.y * BM;
    int n0 = blockIdx.x * BN;

    float acc[8][4];
#pragma unroll
    for (int u = 0; u < 8; u++)
#pragma unroll
        for (int v = 0; v < 4; v++) acc[u][v] = 0.f;

    int ar = tid >> 1;              // 0..127
    int acol = (tid & 1) * 8;       // 0 or 8
    int wr = tid >> 2;              // 0..63
    int wcol = (tid & 3) * 4;       // 0,4,8,12

    for (int k0 = 0; k0 < K; k0 += BK) {
        // load A tile (transposed into Ast[k][m])
        {
            const float* src = A + (size_t)(m0 + ar) * K + k0 + acol;
            float4 v0 = ((const float4*)src)[0];
            float4 v1 = ((const float4*)src)[1];
            Ast[acol + 0][ar] = v0.x; Ast[acol + 1][ar] = v0.y;
            Ast[acol + 2][ar] = v0.z; Ast[acol + 3][ar] = v0.w;
            Ast[acol + 4][ar] = v1.x; Ast[acol + 5][ar] = v1.y;
            Ast[acol + 6][ar] = v1.z; Ast[acol + 7][ar] = v1.w;
        }
        // load W tile (transposed into Wt[k][n])
        {
            const float* src = W + (size_t)(n0 + wr) * K + k0 + wcol;
            float4 v = *(const float4*)src;
            Wt[wcol + 0][wr] = v.x; Wt[wcol + 1][wr] = v.y;
            Wt[wcol + 2][wr] = v.z; Wt[wcol + 3][wr] = v.w;
        }
        __syncthreads();
#pragma unroll
        for (int kk = 0; kk < BK; kk++) {
            float4 a0 = *(const float4*)&Ast[kk][ty * 8];
            float4 a1 = *(const float4*)&Ast[kk][ty * 8 + 4];
            float4 w  = *(const float4*)&Wt[kk][tx * 4];
            float av[8] = {a0.x, a0.y, a0.z, a0.w, a1.x, a1.y, a1.z, a1.w};
            float wv[4] = {w.x, w.y, w.z, w.w};
#pragma unroll
            for (int u = 0; u < 8; u++)
#pragma unroll
                for (int v = 0; v < 4; v++) acc[u][v] = fmaf(av[u], wv[v], acc[u][v]);
        }
        __syncthreads();
    }
    float bv[4];
#pragma unroll
    for (int v = 0; v < 4; v++) bv[v] = bias[n0 + tx * 4 + v];
#pragma unroll
    for (int u = 0; u < 8; u++) {
        float4 o;
        o.x = acc[u][0] + bv[0]; o.y = acc[u][1] + bv[1];
        o.z = acc[u][2] + bv[2]; o.w = acc[u][3] + bv[3];
        if (ACT == 1) {
            o.x = fmaxf(o.x, 0.f); o.y = fmaxf(o.y, 0.f);
            o.z = fmaxf(o.z, 0.f); o.w = fmaxf(o.w, 0.f);
        }
        *(float4*)&C[(size_t)(m0 + ty * 8 + u) * Dout + n0 + tx * 4] = o;
    }
}

// ---------------- attention score vectors: s_src = h.a[:D], s_dst = h.a[D:] ----------------
template <int D>
__global__ __launch_bounds__(256)
void svec_kernel(const float* __restrict__ h, const float* __restrict__ a,
                 float* __restrict__ ssrc, float* __restrict__ sdst) {
    int lane = threadIdx.x & 31;
    int warp = threadIdx.x >> 5;
    size_t row = (size_t)blockIdx.x * 8 + warp;   // < MTOT
    const float* hr = h + row * D;
    float s = 0.f, d = 0.f;
#pragma unroll
    for (int q = 0; q < D / 32; q++) {
        float v = hr[q * 32 + lane];
        s = fmaf(v, a[q * 32 + lane], s);
        d = fmaf(v, a[D + q * 32 + lane], d);
    }
#pragma unroll
    for (int off = 16; off > 0; off >>= 1) {
        s += __shfl_xor_sync(0xffffffffu, s, off);
        d += __shfl_xor_sync(0xffffffffu, d, off);
    }
    if (lane == 0) { ssrc[row] = s; sdst[row] = d; }
}

// ---------------- GAT attention: warp per row, edge-sparse online softmax ----------------
// out_i = (sum_{j: adj>0} exp(e_ij - m) * h_j) / sum exp(e_ij - m); mask row i >= total.
template <int D, int ACT>
__global__ __launch_bounds__(256)
void gat_att_kernel(const float* __restrict__ h, const float* __restrict__ adj,
                    const float* __restrict__ ssrc, const float* __restrict__ sdst,
                    const int* __restrict__ total, float* __restrict__ out) {
    const int PL = D / 32;           // floats per lane
    int lane = threadIdx.x & 31;
    int warp = threadIdx.x >> 5;
    int b = blockIdx.y;
    int i = blockIdx.x * 8 + warp;
    const float* adjrow = adj + ((size_t)b * NSEQ + i) * NSEQ;
    const float* hb = h + (size_t)b * NSEQ * D;
    float si = ssrc[b * NSEQ + i];
    const float* sd = sdst + b * NSEQ;

    float m = -1e30f, ssum = 0.f;
    int cnt = 0;
    float acc[PL];
#pragma unroll
    for (int q = 0; q < PL; q++) acc[q] = 0.f;

    for (int j0 = 0; j0 < NSEQ; j0 += 32) {
        float av = adjrow[j0 + lane];
        float xv = si + sd[j0 + lane];
        float e = xv > 0.f ? xv : 0.01f * xv;   // leaky_relu 0.01
        unsigned msk = __ballot_sync(0xffffffffu, av > 0.f);
        cnt += __popc(msk);
        while (msk) {
            int src = __ffs(msk) - 1;
            msk &= msk - 1;
            float ej = __shfl_sync(0xffffffffu, e, src);
            float p;
            if (ej > m) {
                float f = __expf(m - ej);
                ssum *= f;
#pragma unroll
                for (int q = 0; q < PL; q++) acc[q] *= f;
                m = ej;
                p = 1.f;
            } else {
                p = __expf(ej - m);
            }
            ssum += p;
            const float4* hj = (const float4*)(hb + (size_t)(j0 + src) * D + lane * PL);
#pragma unroll
            for (int q4 = 0; q4 < PL / 4; q4++) {
                float4 v = hj[q4];
                acc[q4 * 4 + 0] = fmaf(p, v.x, acc[q4 * 4 + 0]);
                acc[q4 * 4 + 1] = fmaf(p, v.y, acc[q4 * 4 + 1]);
                acc[q4 * 4 + 2] = fmaf(p, v.z, acc[q4 * 4 + 2]);
                acc[q4 * 4 + 3] = fmaf(p, v.w, acc[q4 * 4 + 3]);
            }
        }
    }
    float inv;
    if (cnt > 0) {
        inv = 1.f / ssum;
    } else {
        // reference: softmax of all-NEG row is uniform 1/N (never hit with p=0.05, kept for exactness)
#pragma unroll 1
        for (int j = 0; j < NSEQ; j++) {
            const float4* hj = (const float4*)(hb + (size_t)j * D + lane * PL);
#pragma unroll
            for (int q4 = 0; q4 < PL / 4; q4++) {
                float4 v = hj[q4];
                acc[q4 * 4 + 0] += v.x; acc[q4 * 4 + 1] += v.y;
                acc[q4 * 4 + 2] += v.z; acc[q4 * 4 + 3] += v.w;
            }
        }
        inv = 1.f / (float)NSEQ;
    }
    bool on = (i < total[b]);
    float* op = out + ((size_t)b * NSEQ + i) * D + lane * PL;
#pragma unroll
    for (int q4 = 0; q4 < PL / 4; q4++) {
        float4 o;
        o.x = on ? acc[q4 * 4 + 0] * inv : 0.f;
        o.y = on ? acc[q4 * 4 + 1] * inv : 0.f;
        o.z = on ? acc[q4 * 4 + 2] * inv : 0.f;
        o.w = on ? acc[q4 * 4 + 3] * inv : 0.f;
        if (ACT == 1) {
            o.x = fmaxf(o.x, 0.f); o.y = fmaxf(o.y, 0.f);
            o.z = fmaxf(o.z, 0.f); o.w = fmaxf(o.w, 0.f);
        }
        ((float4*)op)[q4] = o;
    }
}

// ---------------- bidirectional GRU scan ----------------
// grid (8 batches, 2 dirs), 192 threads. Whh row per thread in regs (packed f32x2),
// h in smem. Gate order torch: r | z | n.
__global__ __launch_bounds__(192)
void gru_kernel(const float* __restrict__ xf, const float* __restrict__ xb,
                const float* __restrict__ Whh_f, const float* __restrict__ bhh_f,
                const float* __restrict__ Whh_b, const float* __restrict__ bhh_b,
                float* __restrict__ gf, float* __restrict__ gb) {
    int b = blockIdx.x;
    int dir = blockIdx.y;
    const float* xproj = dir ? xb : xf;
    const float* Whh = dir ? Whh_b : Whh_f;
    const float* bhh = dir ? bhh_b : bhh_f;
    float* ys = dir ? gb : gf;
    int j = threadIdx.x;  // 0..191

    __shared__ __align__(16) float sh_h[GRUD];
    __shared__ float sh_g[3 * GRUD];
    __shared__ float sh_xn[GRUD];

    unsigned long long wp[32];
    {
        const float2* wr = (const float2*)(Whh + (size_t)j * GRUD);
#pragma unroll
        for (int q = 0; q < 32; q++) { float2 v = wr[q]; wp[q] = pk2(v.x, v.y); }
    }
    float bj = bhh[j];
    if (j < GRUD) sh_h[j] = 0.f;

    const float* xbase = xproj + (size_t)b * NSEQ * (3 * GRUD);
    float* ybase = ys + (size_t)b * NSEQ * GRUD;

    for (int s = 0; s < NSEQ; s++) {
        int t = dir ? (NSEQ - 1 - s) : s;
        float xt = xbase[(size_t)t * (3 * GRUD) + j];
        __syncthreads();
        const unsigned long long* hp = (const unsigned long long*)sh_h;
        unsigned long long a0 = 0ull, a1 = 0ull, a2 = 0ull, a3 = 0ull;
#pragma unroll
        for (int q = 0; q < 32; q += 4) {
            a0 = ffma2(wp[q + 0], hp[q + 0], a0);
            a1 = ffma2(wp[q + 1], hp[q + 1], a1);
            a2 = ffma2(wp[q + 2], hp[q + 2], a2);
            a3 = ffma2(wp[q + 3], hp[q + 3], a3);
        }
        unsigned long long sA = fadd2(fadd2(a0, a1), fadd2(a2, a3));
        float lo, hi;
        upk2(sA, lo, hi);
        float gh = lo + hi + bj;
        if (j < 2 * GRUD) sh_g[j] = xt + gh;
        else { sh_g[j] = gh; sh_xn[j - 2 * GRUD] = xt; }
        __syncthreads();
        if (j < GRUD) {
            float r = 1.f / (1.f + __expf(-sh_g[j]));
            float z = 1.f / (1.f + __expf(-sh_g[GRUD + j]));
            float n = tanhf(sh_xn[j] + r * sh_g[2 * GRUD + j]);
            float hn = fmaf(z, sh_h[j] - n, n);   // (1-z)*n + z*h
            sh_h[j] = hn;
            ybase[(size_t)t * GRUD + j] = hn;
        }
    }
}

// ---------------- masked pooling (sum) ----------------
__global__ void zero_pool_kernel(float* __restrict__ p) {
    int t = threadIdx.x;
    if (t < BB * 2 * GRUD) p[t] = 0.f;
}

__global__ void pool_kernel(const float* __restrict__ gf, const float* __restrict__ gb,
                            const int* __restrict__ total, float* __restrict__ pool) {
    int b = blockIdx.x;
    int chunk = blockIdx.y;          // 32 chunks of 64 rows
    int d = threadIdx.x;             // 0..127
    int tot = total[b];
    float s = 0.f;
    int i0 = chunk * 64;
#pragma unroll 4
    for (int i = i0; i < i0 + 64; i++) {
        if (i < tot) {
            float v = (d < GRUD) ? gf[((size_t)b * NSEQ + i) * GRUD + d]
                                 : gb[((size_t)b * NSEQ + i) * GRUD + (d - GRUD)];
            s += v;
        }
    }
    atomicAdd(&pool[b * 2 * GRUD + d], s);
}

// ---------------- head: fusion (pooled, by linearity) + classifier ----------------
__global__ void head_kernel(const float* __restrict__ pool,
                            const float* __restrict__ W_fus, const float* __restrict__ b_fus,
                            const float* __restrict__ W_c1, const float* __restrict__ b_c1,
                            const float* __restrict__ W_c2, const float* __restrict__ b_c2,
                            float* __restrict__ out) {
    int b = blockIdx.x;
    int t = threadIdx.x;  // 128
    __shared__ float sf[GRUD];
    __shared__ float sh1[128];
    __shared__ float sred[4];
    const float invN = 1.0f / (float)NSEQ;
    if (t < GRUD) {
        float s = b_fus[t];
        for (int d = 0; d < 2 * GRUD; d++)
            s = fmaf(W_fus[t * 2 * GRUD + d], pool[b * 2 * GRUD + d] * invN, s);
        sf[t] = s;
    }
    __syncthreads();
    {
        float s = b_c1[t];
        for (int g = 0; g < GRUD; g++) s = fmaf(W_c1[t * GRUD + g], sf[g], s);
        sh1[t] = fmaxf(s, 0.f);
    }
    __syncthreads();
    float v = W_c2[t] * sh1[t];
#pragma unroll
    for (int off = 16; off > 0; off >>= 1) v += __shfl_xor_sync(0xffffffffu, v, off);
    if ((t & 31) == 0) sred[t >> 5] = v;
    __syncthreads();
    if (t == 0) {
        float o = sred[0] + sred[1] + sred[2] + sred[3] + b_c2[0];
        out[b] = 1.f / (1.f + expf(-o));
    }
}

// ---------------- launch ----------------
extern "C" void kernel_launch(void* const* d_in, const int* in_sizes, int n_in,
                              void* d_out, int out_size) {
    const float* req    = (const float*)d_in[0];
    const float* code   = (const float*)d_in[1];
    const float* adj    = (const float*)d_in[2];
    const int*   total  = (const int*)  d_in[3];
    const float* W_proj = (const float*)d_in[4];
    const float* b_proj = (const float*)d_in[5];
    const float* W_g1   = (const float*)d_in[6];
    const float* b_g1   = (const float*)d_in[7];
    const float* a_g1   = (const float*)d_in[8];
    const float* W_g2   = (const float*)d_in[9];
    const float* b_g2   = (const float*)d_in[10];
    const float* a_g2   = (const float*)d_in[11];
    const float* Wih_f  = (const float*)d_in[12];
    const float* Whh_f  = (const float*)d_in[13];
    const float* bih_f  = (const float*)d_in[14];
    const float* bhh_f  = (const float*)d_in[15];
    const float* Wih_b  = (const float*)d_in[16];
    const float* Whh_b  = (const float*)d_in[17];
    const float* bih_b  = (const float*)d_in[18];
    const float* bhh_b  = (const float*)d_in[19];
    const float* W_fus  = (const float*)d_in[20];
    const float* b_fus  = (const float*)d_in[21];
    const float* W_c1   = (const float*)d_in[22];
    const float* b_c1   = (const float*)d_in[23];
    const float* W_c2   = (const float*)d_in[24];
    const float* b_c2   = (const float*)d_in[25];
    float* out = (float*)d_out;

    void *px, *pproj, *ph1, *pg1, *ph2, *pgat, *ps1s, *ps1d, *ps2s, *ps2d;
    void *pxf, *pxb, *pgf, *pgb, *ppool;
    cudaGetSymbolAddress(&px, g_x);
    cudaGetSymbolAddress(&pproj, g_proj);
    cudaGetSymbolAddress(&ph1, g_h1);
    cudaGetSymbolAddress(&pg1, g_g1);
    cudaGetSymbolAddress(&ph2, g_h2);
    cudaGetSymbolAddress(&pgat, g_gat);
    cudaGetSymbolAddress(&ps1s, g_s1s);
    cudaGetSymbolAddress(&ps1d, g_s1d);
    cudaGetSymbolAddress(&ps2s, g_s2s);
    cudaGetSymbolAddress(&ps2d, g_s2d);
    cudaGetSymbolAddress(&pxf, g_xf);
    cudaGetSymbolAddress(&pxb, g_xb);
    cudaGetSymbolAddress(&pgf, g_gf);
    cudaGetSymbolAddress(&pgb, g_gb);
    cudaGetSymbolAddress(&ppool, g_pool);

    float* fx   = (float*)px;
    float* fpro = (float*)pproj;
    float* fh1  = (float*)ph1;
    float* fg1  = (float*)pg1;
    float* fh2  = (float*)ph2;
    float* fgat = (float*)pgat;

    // 1) concat
    {
        size_t tot4 = (size_t)BB * NSEQ * (FEAT / 4);
        concat_kernel<<<(unsigned)((tot4 + 255) / 256), 256>>>(
            (const float4*)req, (const float4*)code, (float4*)px);
    }
    // 2) proj = relu(x @ W_proj^T + b)
    gemm_kernel<1><<<dim3(HIDD / 64, MTOT / 128), 256>>>(fx, W_proj, b_proj, fpro, MTOT, FEAT, HIDD);
    // 3) GAT1: h1 = proj @ W_g1^T + b
    gemm_kernel<0><<<dim3(HIDD / 64, MTOT / 128), 256>>>(fpro, W_g1, b_g1, fh1, MTOT, HIDD, HIDD);
    svec_kernel<HIDD><<<MTOT / 8, 256>>>(fh1, a_g1, (float*)ps1s, (float*)ps1d);
    gat_att_kernel<HIDD, 1><<<dim3(NSEQ / 8, BB), 256>>>(fh1, adj, (const float*)ps1s,
                                                         (const float*)ps1d, total, fg1);
    // 4) GAT2: h2 = g1 @ W_g2^T + b
    gemm_kernel<0><<<dim3(GATD / 64, MTOT / 128), 256>>>(fg1, W_g2, b_g2, fh2, MTOT, HIDD, GATD);
    svec_kernel<GATD><<<MTOT / 8, 256>>>(fh2, a_g2, (float*)ps2s, (float*)ps2d);
    gat_att_kernel<GATD, 0><<<dim3(NSEQ / 8, BB), 256>>>(fh2, adj, (const float*)ps2s,
                                                         (const float*)ps2d, total, fgat);
    // 5) GRU input projections
    gemm_kernel<0><<<dim3((3 * GRUD) / 64, MTOT / 128), 256>>>(fgat, Wih_f, bih_f, (float*)pxf,
                                                               MTOT, GATD, 3 * GRUD);
    gemm_kernel<0><<<dim3((3 * GRUD) / 64, MTOT / 128), 256>>>(fgat, Wih_b, bih_b, (float*)pxb,
                                                               MTOT, GATD, 3 * GRUD);
    // 6) GRU scan, both directions concurrently
    gru_kernel<<<dim3(BB, 2), 192>>>((const float*)pxf, (const float*)pxb,
                                     Whh_f, bhh_f, Whh_b, bhh_b,
                                     (float*)pgf, (float*)pgb);
    // 7) masked mean-pool (sum here, /N in head)
    zero_pool_kernel<<<1, 1024>>>((float*)ppool);
    pool_kernel<<<dim3(BB, 32), 128>>>((const float*)pgf, (const float*)pgb, total, (float*)ppool);
    // 8) fused fusion + classifier
    head_kernel<<<BB, 128>>>((const float*)ppool, W_fus, b_fus, W_c1, b_c1, W_c2, b_c2, out);
}

// round 4
// speedup vs baseline: 1.3716x; 1.3716x over previous
#include <cuda_runtime.h>
#include <math.h>
#include <stdint.h>

// ---------------- problem constants ----------------
static const int BB    = 8;
static const int NR    = 1024;
static const int NSEQ  = 2048;     // N = NR + NC
static const int FEAT  = 768;
static const int HIDD  = 256;
static const int GATD  = 128;
static const int GRUD  = 64;
static const int MTOT  = BB * NSEQ;   // 16384
static const int CAP   = 512;         // max edges per row (p=0.05, mean 102, P(>512)~0)

// ---------------- scratch (static device memory; no allocs) ----------------
__device__ float g_x   [BB * NSEQ * FEAT];
__device__ float g_proj[BB * NSEQ * HIDD];
__device__ float g_h1  [BB * NSEQ * HIDD];
__device__ float g_g1  [BB * NSEQ * HIDD];
__device__ float g_h2  [BB * NSEQ * GATD];
__device__ float g_gat [BB * NSEQ * GATD];
__device__ float g_s1s [BB * NSEQ];
__device__ float g_s1d [BB * NSEQ];
__device__ float g_s2s [BB * NSEQ];
__device__ float g_s2d [BB * NSEQ];
__device__ float g_xall[BB * NSEQ * 384];    // merged GRU input proj (fwd 0..191 | bwd 192..383)
__device__ float g_Wih [384 * GATD];
__device__ float g_bih [384];
__device__ float g_gf  [BB * NSEQ * GRUD];
__device__ float g_gb  [BB * NSEQ * GRUD];
__device__ float g_pool[BB * 2 * GRUD];
__device__ unsigned short g_el [ (size_t)MTOT * CAP ];
__device__ int            g_deg[ MTOT ];

// ---------------- packed f32x2 helpers ----------------
__device__ __forceinline__ unsigned long long pk2(float lo, float hi) {
    unsigned long long r;
    asm("mov.b64 %0, {%1, %2};" : "=l"(r) : "f"(lo), "f"(hi));
    return r;
}
__device__ __forceinline__ void upk2(unsigned long long v, float& lo, float& hi) {
    asm("mov.b64 {%0, %1}, %2;" : "=f"(lo), "=f"(hi) : "l"(v));
}
__device__ __forceinline__ unsigned long long ffma2(unsigned long long a,
                                                    unsigned long long b,
                                                    unsigned long long c) {
    unsigned long long d;
    asm("fma.rn.f32x2 %0, %1, %2, %3;" : "=l"(d) : "l"(a), "l"(b), "l"(c));
    return d;
}
__device__ __forceinline__ unsigned long long fadd2(unsigned long long a,
                                                    unsigned long long b) {
    unsigned long long d;
    asm("add.rn.f32x2 %0, %1, %2;" : "=l"(d) : "l"(a), "l"(b));
    return d;
}
__device__ __forceinline__ float fast_tanh(float x) {
    float y;
    asm("tanh.approx.f32 %0, %1;" : "=f"(y) : "f"(x));
    return y;
}
__device__ __forceinline__ float fast_sig(float x) {
    return fmaf(0.5f, fast_tanh(0.5f * x), 0.5f);
}

// ---------------- concat req||code -> g_x ----------------
__global__ void concat_kernel(const float4* __restrict__ req,
                              const float4* __restrict__ code,
                              float4* __restrict__ x) {
    size_t idx = (size_t)blockIdx.x * blockDim.x + threadIdx.x;
    const size_t TOT = (size_t)BB * NSEQ * (FEAT / 4);
    if (idx >= TOT) return;
    const int ROW4 = FEAT / 4;
    int b   = (int)(idx / ((size_t)NSEQ * ROW4));
    int rem = (int)(idx % ((size_t)NSEQ * ROW4));
    int i   = rem / ROW4;
    int c   = rem % ROW4;
    float4 v;
    if (i < NR) v = req [((size_t)b * NR + i) * ROW4 + c];
    else        v = code[((size_t)b * NR + (i - NR)) * ROW4 + c];
    x[idx] = v;
}

// ---------------- CSR edge-list build (one adj pass) ----------------
__global__ __launch_bounds__(256)
void build_csr_kernel(const float* __restrict__ adj, unsigned short* __restrict__ el,
                      int* __restrict__ deg) {
    int lane = threadIdx.x & 31;
    int warp = threadIdx.x >> 5;
    int row = blockIdx.x * 8 + warp;                 // 0..MTOT-1
    const float* ar = adj + (size_t)row * NSEQ;
    unsigned short* er = el + (size_t)row * CAP;
    int cnt = 0;
    for (int j0 = 0; j0 < NSEQ; j0 += 32) {
        float v = ar[j0 + lane];
        unsigned msk = __ballot_sync(0xffffffffu, v > 0.f);
        int pos = cnt + __popc(msk & ((1u << lane) - 1u));
        if (v > 0.f && pos < CAP) er[pos] = (unsigned short)(j0 + lane);
        cnt += __popc(msk);
    }
    if (lane == 0) deg[row] = cnt < CAP ? cnt : CAP;
}

// ---------------- merge GRU input weights (fwd|bwd) ----------------
__global__ void merge_wih_kernel(const float* __restrict__ Wf, const float* __restrict__ Wb,
                                 const float* __restrict__ bf, const float* __restrict__ bb,
                                 float* __restrict__ W, float* __restrict__ bias) {
    int idx = blockIdx.x * blockDim.x + threadIdx.x;
    if (idx < 384 * GATD) {
        int r = idx / GATD, c = idx % GATD;
        W[idx] = (r < 192) ? Wf[r * GATD + c] : Wb[(r - 192) * GATD + c];
    }
    if (idx < 384) bias[idx] = (idx < 192) ? bf[idx] : bb[idx - 192];
}

// ---------------- SGEMM v2: 128x128x16, double-buffered, 8x8 microtile ----------------
// C[M,Dout] = act(A[M,K] @ W[Dout,K]^T + bias); M%128==0, Dout%128==0, K%16==0.
template <int ACT>
__global__ __launch_bounds__(256)
void gemm128_kernel(const float* __restrict__ A, const float* __restrict__ W,
                    const float* __restrict__ bias, float* __restrict__ C,
                    int M, int K, int Dout) {
    const int BM = 128, BN = 128, BK = 16;
    __shared__ float As[2][BK][BM];
    __shared__ float Bs[2][BK][BN];
    int tid = threadIdx.x;
    int tx = tid & 15;           // n microtile (8 cols)
    int ty = tid >> 4;           // m microtile (8 rows)
    int m0 = blockIdx.y * BM;
    int n0 = blockIdx.x * BN;
    int lr = tid >> 1;           // 0..127 tile row
    int lc = (tid & 1) * 8;      // 0 / 8 col offset

    const float* Aptr = A + (size_t)(m0 + lr) * K + lc;
    const float* Wptr = W + (size_t)(n0 + lr) * K + lc;

    float acc[8][8];
#pragma unroll
    for (int u = 0; u < 8; u++)
#pragma unroll
        for (int v = 0; v < 8; v++) acc[u][v] = 0.f;

    // first tile -> buf 0
    {
        float4 a0 = *(const float4*)Aptr;
        float4 a1 = *(const float4*)(Aptr + 4);
        float4 w0 = *(const float4*)Wptr;
        float4 w1 = *(const float4*)(Wptr + 4);
        As[0][lc + 0][lr] = a0.x; As[0][lc + 1][lr] = a0.y;
        As[0][lc + 2][lr] = a0.z; As[0][lc + 3][lr] = a0.w;
        As[0][lc + 4][lr] = a1.x; As[0][lc + 5][lr] = a1.y;
        As[0][lc + 6][lr] = a1.z; As[0][lc + 7][lr] = a1.w;
        Bs[0][lc + 0][lr] = w0.x; Bs[0][lc + 1][lr] = w0.y;
        Bs[0][lc + 2][lr] = w0.z; Bs[0][lc + 3][lr] = w0.w;
        Bs[0][lc + 4][lr] = w1.x; Bs[0][lc + 5][lr] = w1.y;
        Bs[0][lc + 6][lr] = w1.z; Bs[0][lc + 7][lr] = w1.w;
    }
    __syncthreads();

    int nk = K / BK;
    for (int kt = 0; kt < nk; kt++) {
        int p = kt & 1;
        float4 na0, na1, nw0, nw1;
        bool more = (kt + 1 < nk);
        if (more) {
            const float* ap = Aptr + (size_t)(kt + 1) * BK;
            const float* wp = Wptr + (size_t)(kt + 1) * BK;
            na0 = *(const float4*)ap; na1 = *(const float4*)(ap + 4);
            nw0 = *(const float4*)wp; nw1 = *(const float4*)(wp + 4);
        }
#pragma unroll
        for (int kk = 0; kk < BK; kk++) {
            float4 x0 = *(const float4*)&As[p][kk][ty * 8];
            float4 x1 = *(const float4*)&As[p][kk][ty * 8 + 4];
            float4 y0 = *(const float4*)&Bs[p][kk][tx * 8];
            float4 y1 = *(const float4*)&Bs[p][kk][tx * 8 + 4];
            float av[8] = {x0.x, x0.y, x0.z, x0.w, x1.x, x1.y, x1.z, x1.w};
            float bv[8] = {y0.x, y0.y, y0.z, y0.w, y1.x, y1.y, y1.z, y1.w};
#pragma unroll
            for (int u = 0; u < 8; u++)
#pragma unroll
                for (int v = 0; v < 8; v++)
                    acc[u][v] = fmaf(av[u], bv[v], acc[u][v]);
        }
        if (more) {
            int q = p ^ 1;
            As[q][lc + 0][lr] = na0.x; As[q][lc + 1][lr] = na0.y;
            As[q][lc + 2][lr] = na0.z; As[q][lc + 3][lr] = na0.w;
            As[q][lc + 4][lr] = na1.x; As[q][lc + 5][lr] = na1.y;
            As[q][lc + 6][lr] = na1.z; As[q][lc + 7][lr] = na1.w;
            Bs[q][lc + 0][lr] = nw0.x; Bs[q][lc + 1][lr] = nw0.y;
            Bs[q][lc + 2][lr] = nw0.z; Bs[q][lc + 3][lr] = nw0.w;
            Bs[q][lc + 4][lr] = nw1.x; Bs[q][lc + 5][lr] = nw1.y;
            Bs[q][lc + 6][lr] = nw1.z; Bs[q][lc + 7][lr] = nw1.w;
        }
        __syncthreads();
    }

    float bv0[8];
#pragma unroll
    for (int v = 0; v < 8; v++) bv0[v] = bias[n0 + tx * 8 + v];
#pragma unroll
    for (int u = 0; u < 8; u++) {
        float* cp = C + (size_t)(m0 + ty * 8 + u) * Dout + n0 + tx * 8;
        float4 o0, o1;
        o0.x = acc[u][0] + bv0[0]; o0.y = acc[u][1] + bv0[1];
        o0.z = acc[u][2] + bv0[2]; o0.w = acc[u][3] + bv0[3];
        o1.x = acc[u][4] + bv0[4]; o1.y = acc[u][5] + bv0[5];
        o1.z = acc[u][6] + bv0[6]; o1.w = acc[u][7] + bv0[7];
        if (ACT == 1) {
            o0.x = fmaxf(o0.x, 0.f); o0.y = fmaxf(o0.y, 0.f);
            o0.z = fmaxf(o0.z, 0.f); o0.w = fmaxf(o0.w, 0.f);
            o1.x = fmaxf(o1.x, 0.f); o1.y = fmaxf(o1.y, 0.f);
            o1.z = fmaxf(o1.z, 0.f); o1.w = fmaxf(o1.w, 0.f);
        }
        ((float4*)cp)[0] = o0;
        ((float4*)cp)[1] = o1;
    }
}

// ---------------- attention score vectors ----------------
template <int D>
__global__ __launch_bounds__(256)
void svec_kernel(const float* __restrict__ h, const float* __restrict__ a,
                 float* __restrict__ ssrc, float* __restrict__ sdst) {
    int lane = threadIdx.x & 31;
    int warp = threadIdx.x >> 5;
    size_t row = (size_t)blockIdx.x * 8 + warp;
    const float* hr = h + row * D;
    float s = 0.f, d = 0.f;
#pragma unroll
    for (int q = 0; q < D / 32; q++) {
        float v = hr[q * 32 + lane];
        s = fmaf(v, a[q * 32 + lane], s);
        d = fmaf(v, a[D + q * 32 + lane], d);
    }
#pragma unroll
    for (int off = 16; off > 0; off >>= 1) {
        s += __shfl_xor_sync(0xffffffffu, s, off);
        d += __shfl_xor_sync(0xffffffffu, d, off);
    }
    if (lane == 0) { ssrc[row] = s; sdst[row] = d; }
}

// ---------------- GAT attention v2: edge lists, 2-pass softmax, warp per row ----------------
template <int D, int ACT>
__global__ __launch_bounds__(256)
void gat_att2_kernel(const float* __restrict__ h, const unsigned short* __restrict__ el,
                     const int* __restrict__ deg, const float* __restrict__ ssrc,
                     const float* __restrict__ sdst, const int* __restrict__ total,
                     float* __restrict__ out) {
    const int PL = D / 32;
    int lane = threadIdx.x & 31;
    int warp = threadIdx.x >> 5;
    int b = blockIdx.y;
    int i = blockIdx.x * 8 + warp;
    int row = b * NSEQ + i;
    int dg = deg[row];
    const unsigned short* E = el + (size_t)row * CAP;
    const float* hb = h + (size_t)b * NSEQ * D;
    float si = ssrc[row];
    const float* sd = sdst + b * NSEQ;

    float acc[PL];
#pragma unroll
    for (int q = 0; q < PL; q++) acc[q] = 0.f;
    float inv;

    if (dg > 0) {
        // pass 1: row max of leaky_relu scores over edges
        float m = -1e30f;
        for (int e = lane; e < dg; e += 32) {
            int j = E[e];
            float xv = si + sd[j];
            float ev = xv > 0.f ? xv : 0.01f * xv;
            m = fmaxf(m, ev);
        }
#pragma unroll
        for (int off = 16; off > 0; off >>= 1)
            m = fmaxf(m, __shfl_xor_sync(0xffffffffu, m, off));

        // pass 2: p per lane in parallel, broadcast + accumulate h_j
        float ssum = 0.f;
        for (int e0 = 0; e0 < dg; e0 += 32) {
            int e = e0 + lane;
            int j = 0;
            float p = 0.f;
            if (e < dg) {
                j = E[e];
                float xv = si + sd[j];
                float ev = xv > 0.f ? xv : 0.01f * xv;
                p = __expf(ev - m);
            }
            ssum += p;
            int cnt = dg - e0;
            if (cnt > 32) cnt = 32;
            for (int t = 0; t < cnt; t++) {
                float pt = __shfl_sync(0xffffffffu, p, t);
                int jt   = __shfl_sync(0xffffffffu, j, t);
                const float4* hj = (const float4*)(hb + (size_t)jt * D + lane * PL);
#pragma unroll
                for (int q4 = 0; q4 < PL / 4; q4++) {
                    float4 v = hj[q4];
                    acc[q4 * 4 + 0] = fmaf(pt, v.x, acc[q4 * 4 + 0]);
                    acc[q4 * 4 + 1] = fmaf(pt, v.y, acc[q4 * 4 + 1]);
                    acc[q4 * 4 + 2] = fmaf(pt, v.z, acc[q4 * 4 + 2]);
                    acc[q4 * 4 + 3] = fmaf(pt, v.w, acc[q4 * 4 + 3]);
                }
            }
        }
#pragma unroll
        for (int off = 16; off > 0; off >>= 1)
            ssum += __shfl_xor_sync(0xffffffffu, ssum, off);
        inv = 1.f / ssum;
    } else {
        // reference: softmax of all-NEG row is uniform 1/N
#pragma unroll 1
        for (int j = 0; j < NSEQ; j++) {
            const float4* hj = (const float4*)(hb + (size_t)j * D + lane * PL);
#pragma unroll
            for (int q4 = 0; q4 < PL / 4; q4++) {
                float4 v = hj[q4];
                acc[q4 * 4 + 0] += v.x; acc[q4 * 4 + 1] += v.y;
                acc[q4 * 4 + 2] += v.z; acc[q4 * 4 + 3] += v.w;
            }
        }
        inv = 1.f / (float)NSEQ;
    }

    bool on = (i < total[b]);
    float* op = out + ((size_t)row) * D + lane * PL;
#pragma unroll
    for (int q4 = 0; q4 < PL / 4; q4++) {
        float4 o;
        o.x = on ? acc[q4 * 4 + 0] * inv : 0.f;
        o.y = on ? acc[q4 * 4 + 1] * inv : 0.f;
        o.z = on ? acc[q4 * 4 + 2] * inv : 0.f;
        o.w = on ? acc[q4 * 4 + 3] * inv : 0.f;
        if (ACT == 1) {
            o.x = fmaxf(o.x, 0.f); o.y = fmaxf(o.y, 0.f);
            o.z = fmaxf(o.z, 0.f); o.w = fmaxf(o.w, 0.f);
        }
        ((float4*)op)[q4] = o;
    }
}

// ---------------- bidirectional GRU scan (prefetched x, MUFU tanh) ----------------
__global__ __launch_bounds__(192)
void gru_kernel(const float* __restrict__ xall,
                const float* __restrict__ Whh_f, const float* __restrict__ bhh_f,
                const float* __restrict__ Whh_b, const float* __restrict__ bhh_b,
                float* __restrict__ gf, float* __restrict__ gb) {
    int b = blockIdx.x;
    int dir = blockIdx.y;
    const float* Whh = dir ? Whh_b : Whh_f;
    const float* bhh = dir ? bhh_b : bhh_f;
    float* ys = dir ? gb : gf;
    int j = threadIdx.x;  // 0..191

    __shared__ __align__(16) float sh_h[GRUD];
    __shared__ float sh_g[3 * GRUD];
    __shared__ float sh_xn[GRUD];

    unsigned long long wp[32];
    {
        const float2* wr = (const float2*)(Whh + (size_t)j * GRUD);
#pragma unroll
        for (int q = 0; q < 32; q++) { float2 v = wr[q]; wp[q] = pk2(v.x, v.y); }
    }
    float bj = bhh[j];
    if (j < GRUD) sh_h[j] = 0.f;

    const float* xbase = xall + (size_t)b * NSEQ * 384 + (dir ? 192 : 0);
    float* ybase = ys + (size_t)b * NSEQ * GRUD;

    int t0 = dir ? (NSEQ - 1) : 0;
    float xt = xbase[(size_t)t0 * 384 + j];

    for (int s = 0; s < NSEQ; s++) {
        int t  = dir ? (NSEQ - 1 - s) : s;
        float xtn = 0.f;
        if (s + 1 < NSEQ) {
            int tn = dir ? (NSEQ - 2 - s) : (s + 1);
            xtn = xbase[(size_t)tn * 384 + j];   // prefetch next step
        }
        __syncthreads();
        const unsigned long long* hp = (const unsigned long long*)sh_h;
        unsigned long long a0 = 0ull, a1 = 0ull, a2 = 0ull, a3 = 0ull;
#pragma unroll
        for (int q = 0; q < 32; q += 4) {
            a0 = ffma2(wp[q + 0], hp[q + 0], a0);
            a1 = ffma2(wp[q + 1], hp[q + 1], a1);
            a2 = ffma2(wp[q + 2], hp[q + 2], a2);
            a3 = ffma2(wp[q + 3], hp[q + 3], a3);
        }
        unsigned long long sA = fadd2(fadd2(a0, a1), fadd2(a2, a3));
        float lo, hi;
        upk2(sA, lo, hi);
        float gh = lo + hi + bj;
        if (j < 2 * GRUD) sh_g[j] = xt + gh;
        else { sh_g[j] = gh; sh_xn[j - 2 * GRUD] = xt; }
        __syncthreads();
        if (j < GRUD) {
            float r = fast_sig(sh_g[j]);
            float z = fast_sig(sh_g[GRUD + j]);
            float n = fast_tanh(fmaf(r, sh_g[2 * GRUD + j], sh_xn[j]));
            float hn = fmaf(z, sh_h[j] - n, n);   // (1-z)*n + z*h
            sh_h[j] = hn;
            ybase[(size_t)t * GRUD + j] = hn;
        }
        xt = xtn;
    }
}

// ---------------- masked pooling ----------------
__global__ void zero_pool_kernel(float* __restrict__ p) {
    int t = threadIdx.x;
    if (t < BB * 2 * GRUD) p[t] = 0.f;
}

__global__ void pool_kernel(const float* __restrict__ gf, const float* __restrict__ gb,
                            const int* __restrict__ total, float* __restrict__ pool) {
    int b = blockIdx.x;
    int chunk = blockIdx.y;
    int d = threadIdx.x;             // 0..127
    int tot = total[b];
    float s = 0.f;
    int i0 = chunk * 64;
#pragma unroll 4
    for (int i = i0; i < i0 + 64; i++) {
        if (i < tot) {
            float v = (d < GRUD) ? gf[((size_t)b * NSEQ + i) * GRUD + d]
                                 : gb[((size_t)b * NSEQ + i) * GRUD + (d - GRUD)];
            s += v;
        }
    }
    atomicAdd(&pool[b * 2 * GRUD + d], s);
}

// ---------------- head: fusion (by linearity of mean) + classifier ----------------
__global__ void head_kernel(const float* __restrict__ pool,
                            const float* __restrict__ W_fus, const float* __restrict__ b_fus,
                            const float* __restrict__ W_c1, const float* __restrict__ b_c1,
                            const float* __restrict__ W_c2, const float* __restrict__ b_c2,
                            float* __restrict__ out) {
    int b = blockIdx.x;
    int t = threadIdx.x;  // 128
    __shared__ float sf[GRUD];
    __shared__ float sh1[128];
    __shared__ float sred[4];
    const float invN = 1.0f / (float)NSEQ;
    if (t < GRUD) {
        float s = b_fus[t];
        for (int d = 0; d < 2 * GRUD; d++)
            s = fmaf(W_fus[t * 2 * GRUD + d], pool[b * 2 * GRUD + d] * invN, s);
        sf[t] = s;
    }
    __syncthreads();
    {
        float s = b_c1[t];
        for (int g = 0; g < GRUD; g++) s = fmaf(W_c1[t * GRUD + g], sf[g], s);
        sh1[t] = fmaxf(s, 0.f);
    }
    __syncthreads();
    float v = W_c2[t] * sh1[t];
#pragma unroll
    for (int off = 16; off > 0; off >>= 1) v += __shfl_xor_sync(0xffffffffu, v, off);
    if ((t & 31) == 0) sred[t >> 5] = v;
    __syncthreads();
    if (t == 0) {
        float o = sred[0] + sred[1] + sred[2] + sred[3] + b_c2[0];
        out[b] = 1.f / (1.f + expf(-o));
    }
}

// ---------------- launch ----------------
extern "C" void kernel_launch(void* const* d_in, const int* in_sizes, int n_in,
                              void* d_out, int out_size) {
    const float* req    = (const float*)d_in[0];
    const float* code   = (const float*)d_in[1];
    const float* adj    = (const float*)d_in[2];
    const int*   total  = (const int*)  d_in[3];
    const float* W_proj = (const float*)d_in[4];
    const float* b_proj = (const float*)d_in[5];
    const float* W_g1   = (const float*)d_in[6];
    const float* b_g1   = (const float*)d_in[7];
    const float* a_g1   = (const float*)d_in[8];
    const float* W_g2   = (const float*)d_in[9];
    const float* b_g2   = (const float*)d_in[10];
    const float* a_g2   = (const float*)d_in[11];
    const float* Wih_f  = (const float*)d_in[12];
    const float* Whh_f  = (const float*)d_in[13];
    const float* bih_f  = (const float*)d_in[14];
    const float* bhh_f  = (const float*)d_in[15];
    const float* Wih_b  = (const float*)d_in[16];
    const float* Whh_b  = (const float*)d_in[17];
    const float* bih_b  = (const float*)d_in[18];
    const float* bhh_b  = (const float*)d_in[19];
    const float* W_fus  = (const float*)d_in[20];
    const float* b_fus  = (const float*)d_in[21];
    const float* W_c1   = (const float*)d_in[22];
    const float* b_c1   = (const float*)d_in[23];
    const float* W_c2   = (const float*)d_in[24];
    const float* b_c2   = (const float*)d_in[25];
    float* out = (float*)d_out;

    void *px, *pproj, *ph1, *pg1, *ph2, *pgat, *ps1s, *ps1d, *ps2s, *ps2d;
    void *pxall, *pWih, *pbih, *pgf, *pgb, *ppool, *pel, *pdeg;
    cudaGetSymbolAddress(&px, g_x);
    cudaGetSymbolAddress(&pproj, g_proj);
    cudaGetSymbolAddress(&ph1, g_h1);
    cudaGetSymbolAddress(&pg1, g_g1);
    cudaGetSymbolAddress(&ph2, g_h2);
    cudaGetSymbolAddress(&pgat, g_gat);
    cudaGetSymbolAddress(&ps1s, g_s1s);
    cudaGetSymbolAddress(&ps1d, g_s1d);
    cudaGetSymbolAddress(&ps2s, g_s2s);
    cudaGetSymbolAddress(&ps2d, g_s2d);
    cudaGetSymbolAddress(&pxall, g_xall);
    cudaGetSymbolAddress(&pWih, g_Wih);
    cudaGetSymbolAddress(&pbih, g_bih);
    cudaGetSymbolAddress(&pgf, g_gf);
    cudaGetSymbolAddress(&pgb, g_gb);
    cudaGetSymbolAddress(&ppool, g_pool);
    cudaGetSymbolAddress(&pel, g_el);
    cudaGetSymbolAddress(&pdeg, g_deg);

    float* fx   = (float*)px;
    float* fpro = (float*)pproj;
    float* fh1  = (float*)ph1;
    float* fg1  = (float*)pg1;
    float* fh2  = (float*)ph2;
    float* fgat = (float*)pgat;
    unsigned short* fel = (unsigned short*)pel;
    int* fdeg = (int*)pdeg;

    // 0) CSR build (single adj pass) + weight merge
    build_csr_kernel<<<MTOT / 8, 256>>>(adj, fel, fdeg);
    merge_wih_kernel<<<(384 * GATD + 255) / 256, 256>>>(Wih_f, Wih_b, bih_f, bih_b,
                                                        (float*)pWih, (float*)pbih);
    // 1) concat
    {
        size_t tot4 = (size_t)BB * NSEQ * (FEAT / 4);
        concat_kernel<<<(unsigned)((tot4 + 255) / 256), 256>>>(
            (const float4*)req, (const float4*)code, (float4*)px);
    }
    // 2) proj = relu(x @ W_proj^T + b)
    gemm128_kernel<1><<<dim3(HIDD / 128, MTOT / 128), 256>>>(fx, W_proj, b_proj, fpro,
                                                             MTOT, FEAT, HIDD);
    // 3) GAT1
    gemm128_kernel<0><<<dim3(HIDD / 128, MTOT / 128), 256>>>(fpro, W_g1, b_g1, fh1,
                                                             MTOT, HIDD, HIDD);
    svec_kernel<HIDD><<<MTOT / 8, 256>>>(fh1, a_g1, (float*)ps1s, (float*)ps1d);
    gat_att2_kernel<HIDD, 1><<<dim3(NSEQ / 8, BB), 256>>>(fh1, fel, fdeg, (const float*)ps1s,
                                                          (const float*)ps1d, total, fg1);
    // 4) GAT2
    gemm128_kernel<0><<<dim3(GATD / 128, MTOT / 128), 256>>>(fg1, W_g2, b_g2, fh2,
                                                             MTOT, HIDD, GATD);
    svec_kernel<GATD><<<MTOT / 8, 256>>>(fh2, a_g2, (float*)ps2s, (float*)ps2d);
    gat_att2_kernel<GATD, 0><<<dim3(NSEQ / 8, BB), 256>>>(fh2, fel, fdeg, (const float*)ps2s,
                                                          (const float*)ps2d, total, fgat);
    // 5) merged GRU input projections (fwd|bwd)
    gemm128_kernel<0><<<dim3(384 / 128, MTOT / 128), 256>>>(fgat, (const float*)pWih,
                                                            (const float*)pbih, (float*)pxall,
                                                            MTOT, GATD, 384);
    // 6) GRU scan
    gru_kernel<<<dim3(BB, 2), 192>>>((const float*)pxall, Whh_f, bhh_f, Whh_b, bhh_b,
                                     (float*)pgf, (float*)pgb);
    // 7) masked mean-pool (sum; /N in head)
    zero_pool_kernel<<<1, 1024>>>((float*)ppool);
    pool_kernel<<<dim3(BB, 32), 128>>>((const float*)pgf, (const float*)pgb, total, (float*)ppool);
    // 8) head
    head_kernel<<<BB, 128>>>((const float*)ppool, W_fus, b_fus, W_c1, b_c1, W_c2, b_c2, out);
}